// round 3
// baseline (speedup 1.0000x reference)
#include <cuda_runtime.h>

#define B_    4096
#define NCH   32
#define SIZE_ 512
#define CH    256
#define KTOT  768
#define KCH   32
#define NITER (KTOT / KCH)   // 24

// scratch: fc[b][c] = sum_n sigmoid(f_logit) * c_k
__device__ float g_fc[B_ * CH];

__device__ __forceinline__ unsigned int tf32b(float x) {
    unsigned int u;
    asm("cvt.rna.tf32.f32 %0, %1;" : "=r"(u) : "f"(x));
    return u;
}

__device__ __forceinline__ float sigf(float x) { return 1.0f / (1.0f + expf(-x)); }

__device__ __forceinline__ void mma8(float* d, const unsigned int* a, const unsigned int* b) {
    asm volatile(
        "mma.sync.aligned.m16n8k8.row.col.f32.tf32.tf32.f32 "
        "{%0,%1,%2,%3}, {%4,%5,%6,%7}, {%8,%9}, {%0,%1,%2,%3};\n"
        : "+f"(d[0]), "+f"(d[1]), "+f"(d[2]), "+f"(d[3])
        : "r"(a[0]), "r"(a[1]), "r"(a[2]), "r"(a[3]), "r"(b[0]), "r"(b[1]));
}

// ---------------------------------------------------------------------------
// Kernel 1: h_tilde[b][c] = sum_n z_children[b][n][c]  (c in [0,256))
// Writes directly into the h_tilde region of d_out.
// ---------------------------------------------------------------------------
__global__ void __launch_bounds__(256) htilde_kernel(const float* __restrict__ zc,
                                                     float* __restrict__ ht) {
    const int b = blockIdx.x;
    const int c = threadIdx.x;
    const float* p = zc + (size_t)b * NCH * SIZE_ + c;
    float s = 0.0f;
#pragma unroll
    for (int n = 0; n < NCH; n++) s += p[(size_t)n * SIZE_];
    ht[(size_t)b * CH + c] = s;
}

// ---------------------------------------------------------------------------
// Kernel 2: f-gate GEMM (131072 x 768 @ 768 x 256) fused with
//           fc[b][c] = sum_n sigmoid(logit[b][n][c]) * c_k[b][n][c]
// CTA tile: M=128 rows (4 batch x 32 children), N=64 cols, K chunk 32.
// 8 warps in 4x2 layout; warp wm's 32 rows == batch element (blockIdx.y*4+wm).
// ---------------------------------------------------------------------------
__global__ void __launch_bounds__(256, 2)
fgate_kernel(const float* __restrict__ zn, const float* __restrict__ zc,
             const float* __restrict__ Wf, const float* __restrict__ Uf,
             const float* __restrict__ bfv) {
    __shared__ unsigned int As[128][36];
    __shared__ unsigned int Bs[64][36];

    const int tid  = threadIdx.x;
    const int warp = tid >> 5, lane = tid & 31;
    const int g = lane >> 2, t = lane & 3;
    const int wm = warp >> 1, wn = warp & 1;
    const int rowBase = blockIdx.y * 128;   // global child-row base (b*32+n)
    const int colBase = blockIdx.x * 64;    // output gate column base

    float acc[2][4][4];
#pragma unroll
    for (int mi = 0; mi < 2; mi++)
#pragma unroll
        for (int ni = 0; ni < 4; ni++)
#pragma unroll
            for (int e = 0; e < 4; e++) acc[mi][ni][e] = 0.0f;

    float4 aR[4];
    float4 bR[2];

    // prefetch chunk 0 (k0 = 0 -> z_node / W_f)
#pragma unroll
    for (int i = 0; i < 4; i++) {
        int idx = tid + i * 256, row = idx >> 3, c4 = (idx & 7) << 2;
        aR[i] = *reinterpret_cast<const float4*>(zn + (size_t)(rowBase + row) * SIZE_ + c4);
    }
#pragma unroll
    for (int i = 0; i < 2; i++) {
        int idx = tid + i * 256, row = idx >> 3, c4 = (idx & 7) << 2;
        bR[i] = *reinterpret_cast<const float4*>(Wf + (size_t)(colBase + row) * SIZE_ + c4);
    }

    for (int ck = 0; ck < NITER; ck++) {
        __syncthreads();  // buffer free (readers of previous chunk done)
#pragma unroll
        for (int i = 0; i < 4; i++) {
            int idx = tid + i * 256, row = idx >> 3, c4 = (idx & 7) << 2;
            As[row][c4 + 0] = tf32b(aR[i].x);
            As[row][c4 + 1] = tf32b(aR[i].y);
            As[row][c4 + 2] = tf32b(aR[i].z);
            As[row][c4 + 3] = tf32b(aR[i].w);
        }
#pragma unroll
        for (int i = 0; i < 2; i++) {
            int idx = tid + i * 256, row = idx >> 3, c4 = (idx & 7) << 2;
            Bs[row][c4 + 0] = tf32b(bR[i].x);
            Bs[row][c4 + 1] = tf32b(bR[i].y);
            Bs[row][c4 + 2] = tf32b(bR[i].z);
            Bs[row][c4 + 3] = tf32b(bR[i].w);
        }
        __syncthreads();  // buffer ready

        if (ck + 1 < NITER) {  // prefetch next chunk (overlaps with MMA below)
            int k0 = (ck + 1) * KCH;
#pragma unroll
            for (int i = 0; i < 4; i++) {
                int idx = tid + i * 256, row = idx >> 3, c4 = (idx & 7) << 2;
                const float* src = (k0 < SIZE_)
                    ? zn + (size_t)(rowBase + row) * SIZE_ + k0 + c4
                    : zc + (size_t)(rowBase + row) * SIZE_ + (k0 - SIZE_) + c4;  // h_k
                aR[i] = *reinterpret_cast<const float4*>(src);
            }
#pragma unroll
            for (int i = 0; i < 2; i++) {
                int idx = tid + i * 256, row = idx >> 3, c4 = (idx & 7) << 2;
                const float* src = (k0 < SIZE_)
                    ? Wf + (size_t)(colBase + row) * SIZE_ + k0 + c4
                    : Uf + (size_t)(colBase + row) * CH + (k0 - SIZE_) + c4;
                bR[i] = *reinterpret_cast<const float4*>(src);
            }
        }

#pragma unroll
        for (int ks = 0; ks < 4; ks++) {
            const int k = ks * 8;
            unsigned int af[2][4], bf2[4][2];
#pragma unroll
            for (int mi = 0; mi < 2; mi++) {
                int r0 = wm * 32 + mi * 16 + g;
                af[mi][0] = As[r0][k + t];
                af[mi][1] = As[r0 + 8][k + t];
                af[mi][2] = As[r0][k + t + 4];
                af[mi][3] = As[r0 + 8][k + t + 4];
            }
#pragma unroll
            for (int ni = 0; ni < 4; ni++) {
                int c0 = wn * 32 + ni * 8 + g;
                bf2[ni][0] = Bs[c0][k + t];
                bf2[ni][1] = Bs[c0][k + t + 4];
            }
#pragma unroll
            for (int mi = 0; mi < 2; mi++)
#pragma unroll
                for (int ni = 0; ni < 4; ni++) mma8(acc[mi][ni], af[mi], bf2[ni]);
        }
    }

    // Epilogue: sigmoid, multiply by c_k, reduce over the 32 children (one warp = one b)
    const int bGlob = blockIdx.y * 4 + wm;
#pragma unroll
    for (int ni = 0; ni < 4; ni++) {
        const int colG = colBase + wn * 32 + ni * 8 + 2 * t;
        const float2 bias = *reinterpret_cast<const float2*>(bfv + colG);
        float p0 = 0.0f, p1 = 0.0f;
#pragma unroll
        for (int mi = 0; mi < 2; mi++) {
            const int n0 = mi * 16 + g, n1 = n0 + 8;
            const float2 ck0 = *reinterpret_cast<const float2*>(
                zc + (size_t)(bGlob * NCH + n0) * SIZE_ + CH + colG);
            const float2 ck1 = *reinterpret_cast<const float2*>(
                zc + (size_t)(bGlob * NCH + n1) * SIZE_ + CH + colG);
            p0 += sigf(acc[mi][ni][0] + bias.x) * ck0.x + sigf(acc[mi][ni][2] + bias.x) * ck1.x;
            p1 += sigf(acc[mi][ni][1] + bias.y) * ck0.y + sigf(acc[mi][ni][3] + bias.y) * ck1.y;
        }
#pragma unroll
        for (int s = 4; s < 32; s <<= 1) {
            p0 += __shfl_xor_sync(0xffffffffu, p0, s);
            p1 += __shfl_xor_sync(0xffffffffu, p1, s);
        }
        if (g == 0) {
            float2 v;
            v.x = p0;
            v.y = p1;
            *reinterpret_cast<float2*>(g_fc + (size_t)bGlob * CH + colG) = v;
        }
    }
}

// ---------------------------------------------------------------------------
// Kernel 3: i/o/u gates: [z0 | h_tilde] (4096x768) @ 3x (768x256) weights,
// fused gating epilogue -> out[:, :256]=h_j, out[:, 256:]=c_j
// CTA tile M=128 (batch rows) x N=64, three accumulator sets (i, o, u).
// ---------------------------------------------------------------------------
__global__ void __launch_bounds__(256, 1)
iou_kernel(const float* __restrict__ zn, const float* __restrict__ ht,
           const float* __restrict__ Wi, const float* __restrict__ Ui, const float* __restrict__ bi,
           const float* __restrict__ Wo, const float* __restrict__ Uo, const float* __restrict__ bo,
           const float* __restrict__ Wu, const float* __restrict__ Uu, const float* __restrict__ bu,
           float* __restrict__ out) {
    __shared__ unsigned int As[128][36];
    __shared__ unsigned int Bs[3][64][36];

    const int tid  = threadIdx.x;
    const int warp = tid >> 5, lane = tid & 31;
    const int g = lane >> 2, t = lane & 3;
    const int wm = warp >> 1, wn = warp & 1;
    const int rowBase = blockIdx.y * 128;  // batch row base
    const int colBase = blockIdx.x * 64;

    const float* W[3] = {Wi, Wo, Wu};
    const float* U[3] = {Ui, Uo, Uu};

    float acc[3][2][4][4];
#pragma unroll
    for (int gi = 0; gi < 3; gi++)
#pragma unroll
        for (int mi = 0; mi < 2; mi++)
#pragma unroll
            for (int ni = 0; ni < 4; ni++)
#pragma unroll
                for (int e = 0; e < 4; e++) acc[gi][mi][ni][e] = 0.0f;

    float4 aR[4];
    float4 bR[3][2];

    // prefetch chunk 0
#pragma unroll
    for (int i = 0; i < 4; i++) {
        int idx = tid + i * 256, row = idx >> 3, c4 = (idx & 7) << 2;
        aR[i] = *reinterpret_cast<const float4*>(zn + (size_t)(rowBase + row) * (NCH * SIZE_) + c4);
    }
#pragma unroll
    for (int gi = 0; gi < 3; gi++)
#pragma unroll
        for (int i = 0; i < 2; i++) {
            int idx = tid + i * 256, row = idx >> 3, c4 = (idx & 7) << 2;
            bR[gi][i] = *reinterpret_cast<const float4*>(W[gi] + (size_t)(colBase + row) * SIZE_ + c4);
        }

    for (int ck = 0; ck < NITER; ck++) {
        __syncthreads();
#pragma unroll
        for (int i = 0; i < 4; i++) {
            int idx = tid + i * 256, row = idx >> 3, c4 = (idx & 7) << 2;
            As[row][c4 + 0] = tf32b(aR[i].x);
            As[row][c4 + 1] = tf32b(aR[i].y);
            As[row][c4 + 2] = tf32b(aR[i].z);
            As[row][c4 + 3] = tf32b(aR[i].w);
        }
#pragma unroll
        for (int gi = 0; gi < 3; gi++)
#pragma unroll
            for (int i = 0; i < 2; i++) {
                int idx = tid + i * 256, row = idx >> 3, c4 = (idx & 7) << 2;
                Bs[gi][row][c4 + 0] = tf32b(bR[gi][i].x);
                Bs[gi][row][c4 + 1] = tf32b(bR[gi][i].y);
                Bs[gi][row][c4 + 2] = tf32b(bR[gi][i].z);
                Bs[gi][row][c4 + 3] = tf32b(bR[gi][i].w);
            }
        __syncthreads();

        if (ck + 1 < NITER) {
            int k0 = (ck + 1) * KCH;
#pragma unroll
            for (int i = 0; i < 4; i++) {
                int idx = tid + i * 256, row = idx >> 3, c4 = (idx & 7) << 2;
                const float* src = (k0 < SIZE_)
                    ? zn + (size_t)(rowBase + row) * (NCH * SIZE_) + k0 + c4      // z0
                    : ht + (size_t)(rowBase + row) * CH + (k0 - SIZE_) + c4;      // h_tilde
                aR[i] = *reinterpret_cast<const float4*>(src);
            }
#pragma unroll
            for (int gi = 0; gi < 3; gi++)
#pragma unroll
                for (int i = 0; i < 2; i++) {
                    int idx = tid + i * 256, row = idx >> 3, c4 = (idx & 7) << 2;
                    const float* src = (k0 < SIZE_)
                        ? W[gi] + (size_t)(colBase + row) * SIZE_ + k0 + c4
                        : U[gi] + (size_t)(colBase + row) * CH + (k0 - SIZE_) + c4;
                    bR[gi][i] = *reinterpret_cast<const float4*>(src);
                }
        }

#pragma unroll
        for (int ks = 0; ks < 4; ks++) {
            const int k = ks * 8;
            unsigned int af[2][4];
#pragma unroll
            for (int mi = 0; mi < 2; mi++) {
                int r0 = wm * 32 + mi * 16 + g;
                af[mi][0] = As[r0][k + t];
                af[mi][1] = As[r0 + 8][k + t];
                af[mi][2] = As[r0][k + t + 4];
                af[mi][3] = As[r0 + 8][k + t + 4];
            }
#pragma unroll
            for (int gi = 0; gi < 3; gi++) {
                unsigned int bf2[4][2];
#pragma unroll
                for (int ni = 0; ni < 4; ni++) {
                    int c0 = wn * 32 + ni * 8 + g;
                    bf2[ni][0] = Bs[gi][c0][k + t];
                    bf2[ni][1] = Bs[gi][c0][k + t + 4];
                }
#pragma unroll
                for (int mi = 0; mi < 2; mi++)
#pragma unroll
                    for (int ni = 0; ni < 4; ni++) mma8(acc[gi][mi][ni], af[mi], bf2[ni]);
            }
        }
    }

    // Epilogue: gating + writeback
#pragma unroll
    for (int ni = 0; ni < 4; ni++) {
        const int colG = colBase + wn * 32 + ni * 8 + 2 * t;
        const float2 bi2 = *reinterpret_cast<const float2*>(bi + colG);
        const float2 bo2 = *reinterpret_cast<const float2*>(bo + colG);
        const float2 bu2 = *reinterpret_cast<const float2*>(bu + colG);
#pragma unroll
        for (int mi = 0; mi < 2; mi++) {
            const int rb0 = rowBase + wm * 32 + mi * 16 + g;
            const int rb1 = rb0 + 8;

            // row rb0 -> acc elements 0 (col 2t) and 1 (col 2t+1)
            {
                float iv0 = sigf(acc[0][mi][ni][0] + bi2.x);
                float ov0 = sigf(acc[1][mi][ni][0] + bo2.x);
                float uv0 = tanhf(acc[2][mi][ni][0] + bu2.x);
                float iv1 = sigf(acc[0][mi][ni][1] + bi2.y);
                float ov1 = sigf(acc[1][mi][ni][1] + bo2.y);
                float uv1 = tanhf(acc[2][mi][ni][1] + bu2.y);
                float2 fc = *reinterpret_cast<const float2*>(g_fc + (size_t)rb0 * CH + colG);
                float cj0 = iv0 * uv0 + fc.x;
                float cj1 = iv1 * uv1 + fc.y;
                float2 hv, cv;
                hv.x = ov0 * tanhf(cj0);
                hv.y = ov1 * tanhf(cj1);
                cv.x = cj0;
                cv.y = cj1;
                *reinterpret_cast<float2*>(out + (size_t)rb0 * SIZE_ + colG) = hv;
                *reinterpret_cast<float2*>(out + (size_t)rb0 * SIZE_ + CH + colG) = cv;
            }
            // row rb1 -> acc elements 2 and 3
            {
                float iv0 = sigf(acc[0][mi][ni][2] + bi2.x);
                float ov0 = sigf(acc[1][mi][ni][2] + bo2.x);
                float uv0 = tanhf(acc[2][mi][ni][2] + bu2.x);
                float iv1 = sigf(acc[0][mi][ni][3] + bi2.y);
                float ov1 = sigf(acc[1][mi][ni][3] + bo2.y);
                float uv1 = tanhf(acc[2][mi][ni][3] + bu2.y);
                float2 fc = *reinterpret_cast<const float2*>(g_fc + (size_t)rb1 * CH + colG);
                float cj0 = iv0 * uv0 + fc.x;
                float cj1 = iv1 * uv1 + fc.y;
                float2 hv, cv;
                hv.x = ov0 * tanhf(cj0);
                hv.y = ov1 * tanhf(cj1);
                cv.x = cj0;
                cv.y = cj1;
                *reinterpret_cast<float2*>(out + (size_t)rb1 * SIZE_ + colG) = hv;
                *reinterpret_cast<float2*>(out + (size_t)rb1 * SIZE_ + CH + colG) = cv;
            }
        }
    }
}

extern "C" void kernel_launch(void* const* d_in, const int* in_sizes, int n_in,
                              void* d_out, int out_size) {
    (void)in_sizes; (void)n_in; (void)out_size;
    const float* zn = (const float*)d_in[0];   // z_node     (B, N, 512)
    const float* zc = (const float*)d_in[1];   // z_children (B, N, 512)
    const float* Wi = (const float*)d_in[2];
    const float* Ui = (const float*)d_in[3];
    const float* bi = (const float*)d_in[4];
    const float* Wf = (const float*)d_in[5];
    const float* Uf = (const float*)d_in[6];
    const float* bf = (const float*)d_in[7];
    const float* Wo = (const float*)d_in[8];
    const float* Uo = (const float*)d_in[9];
    const float* bo = (const float*)d_in[10];
    const float* Wu = (const float*)d_in[11];
    const float* Uu = (const float*)d_in[12];
    const float* bu = (const float*)d_in[13];

    float* out = (float*)d_out;                       // (B, 512) : [h_j | c_j]
    float* ht  = out + (size_t)B_ * SIZE_;            // (B, 256) : h_tilde

    htilde_kernel<<<B_, 256>>>(zc, ht);
    fgate_kernel<<<dim3(CH / 64, B_ / 4), 256>>>(zn, zc, Wf, Uf, bf);
    iou_kernel<<<dim3(CH / 64, B_ / 128), 256>>>(zn, ht, Wi, Ui, bi, Wo, Uo, bo, Wu, Uu, bu, out);
}

// round 5
// speedup vs baseline: 1.6100x; 1.6100x over previous
#include <cuda_runtime.h>
#include <cstdint>

#define B_    4096
#define NCH   32
#define SIZE_ 512
#define CH    256
#define KTOT  768
#define KCH   32
#define NITER (KTOT / KCH)   // 24

// scratch: fc[b][c] = sum_n sigmoid(f_logit) * c_k
__device__ float g_fc[B_ * CH];

// ---------------------------------------------------------------------------
// helpers
// ---------------------------------------------------------------------------
__device__ __forceinline__ unsigned int tf32b(float x) {
    unsigned int u;
    asm("cvt.rna.tf32.f32 %0, %1;" : "=r"(u) : "f"(x));
    return u;
}
__device__ __forceinline__ float sigf(float x) { return 1.0f / (1.0f + __expf(-x)); }

__device__ __forceinline__ uint32_t s2u(const void* p) {
    uint32_t a;
    asm("{ .reg .u64 t; cvta.to.shared.u64 t, %1; cvt.u32.u64 %0, t; }" : "=r"(a) : "l"(p));
    return a;
}
__device__ __forceinline__ void cp16(uint32_t dst, const void* src) {
    asm volatile("cp.async.cg.shared.global [%0], [%1], 16;" :: "r"(dst), "l"(src) : "memory");
}
__device__ __forceinline__ void cp_commit() {
    asm volatile("cp.async.commit_group;" ::: "memory");
}
__device__ __forceinline__ void ldsm4(unsigned* r, uint32_t addr) {
    asm volatile("ldmatrix.sync.aligned.m8n8.x4.shared.b16 {%0,%1,%2,%3}, [%4];"
                 : "=r"(r[0]), "=r"(r[1]), "=r"(r[2]), "=r"(r[3]) : "r"(addr));
}
__device__ __forceinline__ void mma8(float* d, const unsigned* a, const unsigned* b) {
    asm volatile(
        "mma.sync.aligned.m16n8k8.row.col.f32.tf32.tf32.f32 "
        "{%0,%1,%2,%3}, {%4,%5,%6,%7}, {%8,%9}, {%0,%1,%2,%3};\n"
        : "+f"(d[0]), "+f"(d[1]), "+f"(d[2]), "+f"(d[3])
        : "r"(a[0]), "r"(a[1]), "r"(a[2]), "r"(a[3]), "r"(b[0]), "r"(b[1]));
}

// ---------------------------------------------------------------------------
// Kernel 1: h_tilde[b][c] = sum_n z_children[b][n][c]
// ---------------------------------------------------------------------------
__global__ void __launch_bounds__(256) htilde_kernel(const float* __restrict__ zc,
                                                     float* __restrict__ ht) {
    const int b = blockIdx.x;
    const int c = threadIdx.x;
    const float* p = zc + (size_t)b * NCH * SIZE_ + c;
    float s = 0.0f;
#pragma unroll
    for (int n = 0; n < NCH; n++) s += p[(size_t)n * SIZE_];
    ht[(size_t)b * CH + c] = s;
}

// ---------------------------------------------------------------------------
// Kernel 2: f-gate GEMM (131072 x 768 @ 768 x 256) + fused child reduction.
// CTA tile M=128 (4 batch x 32 children) x N=128, K streamed in 32-chunks.
// 3-stage cp.async pipeline, XOR-swizzled smem, ldmatrix fragments,
// raw fp32 bits as tf32 operands (truncation rounding).
// 8 warps: wm=warp>>1 (batch/rows), wn=warp&1 (64-col halves).
// ---------------------------------------------------------------------------
#define FG_STAGE_BYTES 32768           // A 16KB + B 16KB
#define FG_SMEM (3 * FG_STAGE_BYTES)   // 98304

__global__ void __launch_bounds__(256, 2)
fgate_kernel(const float* __restrict__ zn, const float* __restrict__ zc,
             const float* __restrict__ Wf, const float* __restrict__ Uf,
             const float* __restrict__ bfv) {
    extern __shared__ char smem[];
    const uint32_t sb = s2u(smem);

    const int tid  = threadIdx.x;
    const int warp = tid >> 5, lane = tid & 31;
    const int g = lane >> 2, t = lane & 3;
    const int j = lane >> 3, r = lane & 7;
    const int wm = warp >> 1, wn = warp & 1;
    const int rowBase = blockIdx.y * 128;   // global child-row base (b*32+n)
    const int colBase = blockIdx.x * 128;   // gate column base

    // ldmatrix lane geometry
    const int rowA  = wm * 32 + ((j & 1) << 3) + r;   // + mi*16
    const int cAsel = j >> 1;
    const int rowBn = wn * 64 + ((j >> 1) << 3) + r;  // + np*16
    const int cBsel = j & 1;

    float acc[2][8][4];
#pragma unroll
    for (int mi = 0; mi < 2; mi++)
#pragma unroll
        for (int ni = 0; ni < 8; ni++)
#pragma unroll
            for (int e = 0; e < 4; e++) acc[mi][ni][e] = 0.0f;

    // ---- cp.async chunk loader ----
    auto load_chunk = [&](int stage, int c) {
        const int k0 = c * KCH;
        const uint32_t smA = sb + stage * FG_STAGE_BYTES;
        const uint32_t smB = smA + 16384;
#pragma unroll
        for (int i = 0; i < 4; i++) {
            int id = tid + i * 256, row = id >> 3, ch = id & 7;
            const float* src = (k0 < SIZE_)
                ? zn + (size_t)(rowBase + row) * SIZE_ + k0 + ch * 4
                : zc + (size_t)(rowBase + row) * SIZE_ + (k0 - SIZE_) + ch * 4;  // h_k
            cp16(smA + row * 128 + (((ch ^ (row & 7))) << 4), src);
        }
#pragma unroll
        for (int i = 0; i < 4; i++) {
            int id = tid + i * 256, row = id >> 3, ch = id & 7;
            const float* src = (k0 < SIZE_)
                ? Wf + (size_t)(colBase + row) * SIZE_ + k0 + ch * 4
                : Uf + (size_t)(colBase + row) * CH + (k0 - SIZE_) + ch * 4;
            cp16(smB + row * 128 + (((ch ^ (row & 7))) << 4), src);
        }
    };

    // prologue: stages 0..2 <- chunks 0..2
    load_chunk(0, 0); cp_commit();
    load_chunk(1, 1); cp_commit();
    load_chunk(2, 2); cp_commit();

    for (int c = 0; c < NITER; c++) {
        const int st = c % 3;
        asm volatile("cp.async.wait_group 2;" ::: "memory");
        __syncthreads();

        const uint32_t smA = sb + st * FG_STAGE_BYTES;
        const uint32_t smB = smA + 16384;

#pragma unroll
        for (int ks = 0; ks < 4; ks++) {
            unsigned af[2][4];
            const uint32_t swA = ((2 * ks + cAsel) ^ r) << 4;
            ldsm4(af[0], smA + (rowA) * 128 + swA);
            ldsm4(af[1], smA + (rowA + 16) * 128 + swA);
            unsigned bf[8][2];
            const uint32_t swB = ((2 * ks + cBsel) ^ r) << 4;
#pragma unroll
            for (int np = 0; np < 4; np++) {
                unsigned tmp[4];
                ldsm4(tmp, smB + (rowBn + np * 16) * 128 + swB);
                bf[2 * np][0] = tmp[0]; bf[2 * np][1] = tmp[1];
                bf[2 * np + 1][0] = tmp[2]; bf[2 * np + 1][1] = tmp[3];
            }
#pragma unroll
            for (int mi = 0; mi < 2; mi++)
#pragma unroll
                for (int ni = 0; ni < 8; ni++) mma8(acc[mi][ni], af[mi], bf[ni]);
        }

        __syncthreads();   // all warps done reading stage st
        if (c + 3 < NITER) load_chunk(st, c + 3);
        cp_commit();       // commit every iteration (possibly empty group)
    }

    // ---- Epilogue: sigmoid(+bias) * c_k, reduce over 32 children ----
    const int bGlob = blockIdx.y * 4 + wm;
#pragma unroll
    for (int ni = 0; ni < 8; ni++) {
        const int colG = colBase + wn * 64 + ni * 8 + 2 * t;
        const float2 bias = *reinterpret_cast<const float2*>(bfv + colG);
        float p0 = 0.0f, p1 = 0.0f;
#pragma unroll
        for (int mi = 0; mi < 2; mi++) {
            const int n0 = mi * 16 + g, n1 = n0 + 8;
            const float2 ck0 = *reinterpret_cast<const float2*>(
                zc + (size_t)(bGlob * NCH + n0) * SIZE_ + CH + colG);
            const float2 ck1 = *reinterpret_cast<const float2*>(
                zc + (size_t)(bGlob * NCH + n1) * SIZE_ + CH + colG);
            p0 += sigf(acc[mi][ni][0] + bias.x) * ck0.x + sigf(acc[mi][ni][2] + bias.x) * ck1.x;
            p1 += sigf(acc[mi][ni][1] + bias.y) * ck0.y + sigf(acc[mi][ni][3] + bias.y) * ck1.y;
        }
#pragma unroll
        for (int s = 4; s < 32; s <<= 1) {
            p0 += __shfl_xor_sync(0xffffffffu, p0, s);
            p1 += __shfl_xor_sync(0xffffffffu, p1, s);
        }
        if (g == 0) {
            float2 v; v.x = p0; v.y = p1;
            *reinterpret_cast<float2*>(g_fc + (size_t)bGlob * CH + colG) = v;
        }
    }
}

// ---------------------------------------------------------------------------
// Kernel 3: i/o/u gates: [z0 | h_tilde] (4096x768) @ 3x (768x256), fused
// gating epilogue -> out[:, :256]=h_j, out[:, 256:]=c_j   (round-3 version)
// ---------------------------------------------------------------------------
__global__ void __launch_bounds__(256, 1)
iou_kernel(const float* __restrict__ zn, const float* __restrict__ ht,
           const float* __restrict__ Wi, const float* __restrict__ Ui, const float* __restrict__ bi,
           const float* __restrict__ Wo, const float* __restrict__ Uo, const float* __restrict__ bo,
           const float* __restrict__ Wu, const float* __restrict__ Uu, const float* __restrict__ bu,
           float* __restrict__ out) {
    __shared__ unsigned int As[128][36];
    __shared__ unsigned int Bs[3][64][36];

    const int tid  = threadIdx.x;
    const int warp = tid >> 5, lane = tid & 31;
    const int g = lane >> 2, t = lane & 3;
    const int wm = warp >> 1, wn = warp & 1;
    const int rowBase = blockIdx.y * 128;
    const int colBase = blockIdx.x * 64;

    const float* W[3] = {Wi, Wo, Wu};
    const float* U[3] = {Ui, Uo, Uu};

    float acc[3][2][4][4];
#pragma unroll
    for (int gi = 0; gi < 3; gi++)
#pragma unroll
        for (int mi = 0; mi < 2; mi++)
#pragma unroll
            for (int ni = 0; ni < 4; ni++)
#pragma unroll
                for (int e = 0; e < 4; e++) acc[gi][mi][ni][e] = 0.0f;

    float4 aR[4];
    float4 bR[3][2];

#pragma unroll
    for (int i = 0; i < 4; i++) {
        int idx = tid + i * 256, row = idx >> 3, c4 = (idx & 7) << 2;
        aR[i] = *reinterpret_cast<const float4*>(zn + (size_t)(rowBase + row) * (NCH * SIZE_) + c4);
    }
#pragma unroll
    for (int gi = 0; gi < 3; gi++)
#pragma unroll
        for (int i = 0; i < 2; i++) {
            int idx = tid + i * 256, row = idx >> 3, c4 = (idx & 7) << 2;
            bR[gi][i] = *reinterpret_cast<const float4*>(W[gi] + (size_t)(colBase + row) * SIZE_ + c4);
        }

    for (int ck = 0; ck < NITER; ck++) {
        __syncthreads();
#pragma unroll
        for (int i = 0; i < 4; i++) {
            int idx = tid + i * 256, row = idx >> 3, c4 = (idx & 7) << 2;
            As[row][c4 + 0] = tf32b(aR[i].x);
            As[row][c4 + 1] = tf32b(aR[i].y);
            As[row][c4 + 2] = tf32b(aR[i].z);
            As[row][c4 + 3] = tf32b(aR[i].w);
        }
#pragma unroll
        for (int gi = 0; gi < 3; gi++)
#pragma unroll
            for (int i = 0; i < 2; i++) {
                int idx = tid + i * 256, row = idx >> 3, c4 = (idx & 7) << 2;
                Bs[gi][row][c4 + 0] = tf32b(bR[gi][i].x);
                Bs[gi][row][c4 + 1] = tf32b(bR[gi][i].y);
                Bs[gi][row][c4 + 2] = tf32b(bR[gi][i].z);
                Bs[gi][row][c4 + 3] = tf32b(bR[gi][i].w);
            }
        __syncthreads();

        if (ck + 1 < NITER) {
            int k0 = (ck + 1) * KCH;
#pragma unroll
            for (int i = 0; i < 4; i++) {
                int idx = tid + i * 256, row = idx >> 3, c4 = (idx & 7) << 2;
                const float* src = (k0 < SIZE_)
                    ? zn + (size_t)(rowBase + row) * (NCH * SIZE_) + k0 + c4
                    : ht + (size_t)(rowBase + row) * CH + (k0 - SIZE_) + c4;
                aR[i] = *reinterpret_cast<const float4*>(src);
            }
#pragma unroll
            for (int gi = 0; gi < 3; gi++)
#pragma unroll
                for (int i = 0; i < 2; i++) {
                    int idx = tid + i * 256, row = idx >> 3, c4 = (idx & 7) << 2;
                    const float* src = (k0 < SIZE_)
                        ? W[gi] + (size_t)(colBase + row) * SIZE_ + k0 + c4
                        : U[gi] + (size_t)(colBase + row) * CH + (k0 - SIZE_) + c4;
                    bR[gi][i] = *reinterpret_cast<const float4*>(src);
                }
        }

#pragma unroll
        for (int ks = 0; ks < 4; ks++) {
            const int k = ks * 8;
            unsigned int af[2][4];
#pragma unroll
            for (int mi = 0; mi < 2; mi++) {
                int r0 = wm * 32 + mi * 16 + g;
                af[mi][0] = As[r0][k + t];
                af[mi][1] = As[r0 + 8][k + t];
                af[mi][2] = As[r0][k + t + 4];
                af[mi][3] = As[r0 + 8][k + t + 4];
            }
#pragma unroll
            for (int gi = 0; gi < 3; gi++) {
                unsigned int bf2[4][2];
#pragma unroll
                for (int ni = 0; ni < 4; ni++) {
                    int c0 = wn * 32 + ni * 8 + g;
                    bf2[ni][0] = Bs[gi][c0][k + t];
                    bf2[ni][1] = Bs[gi][c0][k + t + 4];
                }
#pragma unroll
                for (int mi = 0; mi < 2; mi++)
#pragma unroll
                    for (int ni = 0; ni < 4; ni++) mma8(acc[gi][mi][ni], af[mi], bf2[ni]);
            }
        }
    }

#pragma unroll
    for (int ni = 0; ni < 4; ni++) {
        const int colG = colBase + wn * 32 + ni * 8 + 2 * t;
        const float2 bi2 = *reinterpret_cast<const float2*>(bi + colG);
        const float2 bo2 = *reinterpret_cast<const float2*>(bo + colG);
        const float2 bu2 = *reinterpret_cast<const float2*>(bu + colG);
#pragma unroll
        for (int mi = 0; mi < 2; mi++) {
            const int rb0 = rowBase + wm * 32 + mi * 16 + g;
            const int rb1 = rb0 + 8;
            {
                float iv0 = sigf(acc[0][mi][ni][0] + bi2.x);
                float ov0 = sigf(acc[1][mi][ni][0] + bo2.x);
                float uv0 = tanhf(acc[2][mi][ni][0] + bu2.x);
                float iv1 = sigf(acc[0][mi][ni][1] + bi2.y);
                float ov1 = sigf(acc[1][mi][ni][1] + bo2.y);
                float uv1 = tanhf(acc[2][mi][ni][1] + bu2.y);
                float2 fc = *reinterpret_cast<const float2*>(g_fc + (size_t)rb0 * CH + colG);
                float cj0 = iv0 * uv0 + fc.x;
                float cj1 = iv1 * uv1 + fc.y;
                float2 hv, cv;
                hv.x = ov0 * tanhf(cj0); hv.y = ov1 * tanhf(cj1);
                cv.x = cj0; cv.y = cj1;
                *reinterpret_cast<float2*>(out + (size_t)rb0 * SIZE_ + colG) = hv;
                *reinterpret_cast<float2*>(out + (size_t)rb0 * SIZE_ + CH + colG) = cv;
            }
            {
                float iv0 = sigf(acc[0][mi][ni][2] + bi2.x);
                float ov0 = sigf(acc[1][mi][ni][2] + bo2.x);
                float uv0 = tanhf(acc[2][mi][ni][2] + bu2.x);
                float iv1 = sigf(acc[0][mi][ni][3] + bi2.y);
                float ov1 = sigf(acc[1][mi][ni][3] + bo2.y);
                float uv1 = tanhf(acc[2][mi][ni][3] + bu2.y);
                float2 fc = *reinterpret_cast<const float2*>(g_fc + (size_t)rb1 * CH + colG);
                float cj0 = iv0 * uv0 + fc.x;
                float cj1 = iv1 * uv1 + fc.y;
                float2 hv, cv;
                hv.x = ov0 * tanhf(cj0); hv.y = ov1 * tanhf(cj1);
                cv.x = cj0; cv.y = cj1;
                *reinterpret_cast<float2*>(out + (size_t)rb1 * SIZE_ + colG) = hv;
                *reinterpret_cast<float2*>(out + (size_t)rb1 * SIZE_ + CH + colG) = cv;
            }
        }
    }
}

extern "C" void kernel_launch(void* const* d_in, const int* in_sizes, int n_in,
                              void* d_out, int out_size) {
    (void)in_sizes; (void)n_in; (void)out_size;
    const float* zn = (const float*)d_in[0];   // z_node     (B, N, 512)
    const float* zc = (const float*)d_in[1];   // z_children (B, N, 512)
    const float* Wi = (const float*)d_in[2];
    const float* Ui = (const float*)d_in[3];
    const float* bi = (const float*)d_in[4];
    const float* Wf = (const float*)d_in[5];
    const float* Uf = (const float*)d_in[6];
    const float* bf = (const float*)d_in[7];
    const float* Wo = (const float*)d_in[8];
    const float* Uo = (const float*)d_in[9];
    const float* bo = (const float*)d_in[10];
    const float* Wu = (const float*)d_in[11];
    const float* Uu = (const float*)d_in[12];
    const float* bu = (const float*)d_in[13];

    float* out = (float*)d_out;                       // (B, 512) : [h_j | c_j]
    float* ht  = out + (size_t)B_ * SIZE_;            // (B, 256) : h_tilde

    static bool attr_set = false;
    if (!attr_set) {
        cudaFuncSetAttribute(fgate_kernel, cudaFuncAttributeMaxDynamicSharedMemorySize, FG_SMEM);
        attr_set = true;
    }

    // fgate first (independent of h_tilde) so the ncu capture slot lands on it
    fgate_kernel<<<dim3(CH / 128, B_ * NCH / 128), 256, FG_SMEM>>>(zn, zc, Wf, Uf, bf);
    htilde_kernel<<<B_, 256>>>(zc, ht);
    iou_kernel<<<dim3(CH / 64, B_ / 128), 256>>>(zn, ht, Wi, Ui, bi, Wo, Uo, bo, Wu, Uu, bu, out);
}